// round 9
// baseline (speedup 1.0000x reference)
#include <cuda_runtime.h>

#define NBINS 15
#define BS 256
#define NACC (2 + NBINS)
#define GRID 592   // 148 SMs * 4 blocks

// [0]=focal sum (log2 units), [1]=cp sum, [2..16]=per-bin sum of (y - p)
__device__ double g_acc[NACC];
__device__ unsigned g_count;   // zero-initialized at module load

__device__ __forceinline__ float warp_sum(float v) {
#pragma unroll
    for (int o = 16; o > 0; o >>= 1) v += __shfl_down_sync(0xffffffffu, v, o);
    return v;
}

__device__ __forceinline__ void pf_l2(const void* p) {
    asm volatile("prefetch.global.L2 [%0];" :: "l"(p));
}

__device__ __forceinline__ void process1(float p, float u, int t,
                                         float& facc, float& cacc,
                                         float* __restrict__ histcol) {
    bool pos = (t != 0);
    float tf = pos ? 1.0f : 0.0f;

    // focal in log2 units: acc += alpha*(1-pt)^2 * log2(pt+1e-12); *(-ln2) at finalize
    float pt = pos ? p : 1.0f - p;
    float om = 1.0f - pt;
    float om2 = om * om;
    if (!pos) om2 += om2;               // alpha fold: x2 for negatives
    facc = fmaf(om2, __log2f(pt + 1e-12f), facc);

    // confidence penalty: pos&p<tau -> u^2 ; !pos&p>tau -> (1-u)^2
    float v = pos ? u : 1.0f - u;
    bool cond = ((p < 0.7f) == pos);
    if (cond) cacc = fmaf(v, v, cacc);

    // ECE binning: bin = min((int)(p*15), 14); accumulate (y - p)
    int b = (int)fminf(p * 15.0f, 14.0f);
    histcol[b * BS] += tf - p;
}

__device__ __forceinline__ void process4(float4 pv, float4 uv, int4 tv,
                                         float& facc, float& cacc,
                                         float* __restrict__ colA,
                                         float* __restrict__ colB) {
    process1(pv.x, uv.x, tv.x, facc, cacc, colA);
    process1(pv.y, uv.y, tv.y, facc, cacc, colB);
    process1(pv.z, uv.z, tv.z, facc, cacc, colA);
    process1(pv.w, uv.w, tv.w, facc, cacc, colB);
}

__global__ void __launch_bounds__(BS, 4) fcl_main(
    const float* __restrict__ p_hat, const float* __restrict__ u_hat,
    const int* __restrict__ targets, float* __restrict__ out, int n)
{
    __shared__ float histA[NBINS * BS];
    __shared__ float histB[NBINS * BS];
    __shared__ float red[2][BS / 32];
    __shared__ bool is_last;

    const int tid  = threadIdx.x;
    const int lane = tid & 31;
    const int warp = tid >> 5;
    float* colA = &histA[tid];
    float* colB = &histB[tid];

#pragma unroll
    for (int b = 0; b < NBINS; b++) { histA[b * BS + tid] = 0.0f; histB[b * BS + tid] = 0.0f; }
    __syncthreads();

    float facc = 0.0f, cacc = 0.0f;

    const int n4 = n >> 2;
    const float4* __restrict__ p4 = (const float4*)p_hat;
    const float4* __restrict__ u4 = (const float4*)u_hat;
    const int4*   __restrict__ t4 = (const int4*)targets;

    const int stride = GRID * BS;
    const int i0 = blockIdx.x * BS + tid;

    // 2-deep register pipeline (6 LDG.128/warp in flight) + L2 prefetch 4
    // strides ahead: LDGs hit L2 (~250cyc) instead of DRAM (~600cyc), so the
    // 2-stage pipeline fully covers the remaining latency. Prefetches cost no
    // registers, keeping 4 blocks/SM.
    if (i0 < n4) {
        const int iters = (n4 - i0 + stride - 1) / stride;   // >= 1
        float4 pA, uA, pB, uB; int4 tA, tB;
        pA = __ldg(&p4[i0]); uA = __ldg(&u4[i0]); tA = __ldg(&t4[i0]);
        if (iters >= 2) {
            pB = __ldg(&p4[i0 + stride]); uB = __ldg(&u4[i0 + stride]); tB = __ldg(&t4[i0 + stride]);
        }
        int it = 0;
        int i2 = i0 + 2 * stride;
        for (; it + 3 < iters; it += 2, i2 += 2 * stride) {
            // prefetch the tiles the NEXT round's LDGs will want (distance 2 rounds)
            int ipf = i2 + 2 * stride;
            ipf = ipf < n4 ? ipf : n4 - 1;
            pf_l2(&p4[ipf]); pf_l2(&u4[ipf]); pf_l2(&t4[ipf]);
            int ipf2 = i2 + 3 * stride;
            ipf2 = ipf2 < n4 ? ipf2 : n4 - 1;
            pf_l2(&p4[ipf2]); pf_l2(&u4[ipf2]); pf_l2(&t4[ipf2]);

            float4 pn = __ldg(&p4[i2]);
            float4 un = __ldg(&u4[i2]);
            int4   tn = __ldg(&t4[i2]);
            float4 pm = __ldg(&p4[i2 + stride]);
            float4 um = __ldg(&u4[i2 + stride]);
            int4   tm = __ldg(&t4[i2 + stride]);
            process4(pA, uA, tA, facc, cacc, colA, colB);
            process4(pB, uB, tB, facc, cacc, colB, colA);
            pA = pn; uA = un; tA = tn;
            pB = pm; uB = um; tB = tm;
        }
        // epilogue: rem in {1,2,3}
        int rem = iters - it;
        process4(pA, uA, tA, facc, cacc, colA, colB);
        if (rem >= 2) process4(pB, uB, tB, facc, cacc, colB, colA);
        if (rem >= 3) {
            float4 pc = __ldg(&p4[i2]);
            float4 uc = __ldg(&u4[i2]);
            int4   tc = __ldg(&t4[i2]);
            process4(pc, uc, tc, facc, cacc, colA, colB);
        }
    }
    // scalar tail (n not divisible by 4)
    for (int j = (n4 << 2) + i0; j < n; j += stride) {
        process1(p_hat[j], u_hat[j], targets[j], facc, cacc, colA);
    }
    __syncthreads();

    // block-reduce focal / cp
    facc = warp_sum(facc);
    cacc = warp_sum(cacc);
    if (lane == 0) { red[0][warp] = facc; red[1][warp] = cacc; }
    __syncthreads();
    if (warp == 0) {
        float f = (lane < BS / 32) ? red[0][lane] : 0.0f;
        float c = (lane < BS / 32) ? red[1][lane] : 0.0f;
        f = warp_sum(f);
        c = warp_sum(c);
        if (lane == 0) {
            atomicAdd(&g_acc[0], (double)f);
            atomicAdd(&g_acc[1], (double)c);
        }
    }

    // block-reduce each bin column (A+B), one double atomic per bin per block
    for (int b = warp; b < NBINS; b += BS / 32) {
        float s = 0.0f;
#pragma unroll
        for (int j = lane; j < BS; j += 32) s += histA[b * BS + j] + histB[b * BS + j];
        s = warp_sum(s);
        if (lane == 0) atomicAdd(&g_acc[2 + b], (double)s);
    }

    // last-block-done: finalize + reset accumulators for next graph replay
    __threadfence();
    if (tid == 0) {
        unsigned v = atomicInc(&g_count, GRID - 1);  // wraps to 0 on last block
        is_last = (v == GRID - 1);
    }
    __syncthreads();
    if (is_last && tid == 0) {
        double invn  = 1.0 / (double)n;
        double focal = -0.6931471805599453 * g_acc[0] * invn;  // -ln2 * log2-units
        double cp    = g_acc[1] * invn;
        double e     = 0.0;
#pragma unroll
        for (int b = 0; b < NBINS; b++) e += fabs(g_acc[2 + b]);
        e *= invn;
        out[0] = (float)(focal + 6.0 * cp + 5.0 * e);
#pragma unroll
        for (int a = 0; a < NACC; a++) g_acc[a] = 0.0;
    }
}

extern "C" void kernel_launch(void* const* d_in, const int* in_sizes, int n_in,
                              void* d_out, int out_size) {
    const float* p_hat   = (const float*)d_in[0];
    const float* u_hat   = (const float*)d_in[1];
    const int*   targets = (const int*)d_in[2];
    float* out = (float*)d_out;
    int n = in_sizes[0];

    fcl_main<<<GRID, BS>>>(p_hat, u_hat, targets, out, n);
}